// round 17
// baseline (speedup 1.0000x reference)
#include <cuda_runtime.h>
#include <cuda_bf16.h>
#include <cstdint>

#define BINS 10
#define MAXBLK 2048
#define WPB 8                 // warps per block (256 threads)

// Partial bins, laid out [slot][block] so the reducer reads coalesced.
// slot = bin for counts, BINS+bin for loss sums. Plain stores only — no atomics.
static __device__ float g_part[2 * BINS * MAXBLK];

__global__ __launch_bounds__(256) void ghm_rows(
    const float* __restrict__ pred,
    const int*   __restrict__ target,   // JAX int64 -> int32 (x64 disabled)
    int B, int C)
{
    __shared__ float s_cnt[BINS];
    __shared__ float s_sum[BINS];
    if (threadIdx.x < BINS) { s_cnt[threadIdx.x] = 0.0f; s_sum[threadIdx.x] = 0.0f; }
    __syncthreads();

    const int warp = threadIdx.x >> 5;
    const int lane = threadIdx.x & 31;
    const int n4   = C >> 2;                       // 250 for C=1000
    const int nw   = gridDim.x * WPB;

    for (int r = blockIdx.x * WPB + warp; r < B; r += nw) {
        const size_t base = (size_t)r * (size_t)C;
        const float4* __restrict__ p4 = (const float4*)(pred + base);

        float s = 0.0f;
        #pragma unroll 4
        for (int i = lane; i < n4; i += 32) {
            const float4 v = __ldcs(p4 + i);       // read-once stream, evict-first
            s += __expf(v.x) + __expf(v.y) + __expf(v.z) + __expf(v.w);
        }
        for (int j = (n4 << 2) + lane; j < C; j += 32)   // tail (not hit for C=1000)
            s += __expf(pred[base + j]);

        #pragma unroll
        for (int o = 16; o; o >>= 1) s += __shfl_xor_sync(0xffffffffu, s, o);

        if (lane == 0) {
            int t = target[r];
            t = t < 0 ? 0 : (t >= C ? C - 1 : t);  // crash-guard; rel_err exposes misuse
            const float tv = __ldg(pred + base + (size_t)t);
            const float g = 1.0f - __expf(tv) / s;
            int b = (int)floorf(g * 10.0f);
            b = b < 0 ? 0 : (b > BINS - 1 ? BINS - 1 : b);
            const float loss = -tv + __logf(s + 1e-8f);
            atomicAdd(&s_cnt[b], 1.0f);            // smem only — cheap
            atomicAdd(&s_sum[b], loss);
        }
    }

    __syncthreads();
    // Plain stores of this block's partials; fully overwritten every replay.
    if (threadIdx.x < BINS) {
        g_part[threadIdx.x * MAXBLK + blockIdx.x]          = s_cnt[threadIdx.x];
        g_part[(BINS + threadIdx.x) * MAXBLK + blockIdx.x] = s_sum[threadIdx.x];
    }
}

// One block, 640 threads: warp w reduces slot w (coalesced 2048-float row).
__global__ __launch_bounds__(2 * BINS * 32) void ghm_reduce(
    float* __restrict__ out, int nblk)
{
    __shared__ float s_tot[2 * BINS];
    const int warp = threadIdx.x >> 5;     // 0..19 = slot id
    const int lane = threadIdx.x & 31;

    float v = 0.0f;
    const float* src = &g_part[warp * MAXBLK];
    for (int i = lane; i < nblk; i += 32) v += src[i];
    #pragma unroll
    for (int o = 16; o; o >>= 1) v += __shfl_xor_sync(0xffffffffu, v, o);
    if (lane == 0) s_tot[warp] = v;
    __syncthreads();

    if (threadIdx.x == 0) {
        float n_nonempty = 0.0f;
        float tot = 0.0f;
        #pragma unroll
        for (int b = 0; b < BINS; ++b) {
            const float c = s_tot[b];
            const float l = s_tot[BINS + b];
            if (c > 0.0f) { n_nonempty += 1.0f; tot += l / c; }
        }
        out[0] = tot / fmaxf(n_nonempty, 1.0f);
    }
}

extern "C" void kernel_launch(void* const* d_in, const int* in_sizes, int n_in,
                              void* d_out, int out_size) {
    const float* pred   = (const float*)d_in[0];
    const int*   target = (const int*)d_in[1];
    float*       out    = (float*)d_out;

    const int B = in_sizes[1];            // 65536 rows
    const int C = in_sizes[0] / B;        // 1000 classes

    int grid = (B + WPB - 1) / WPB;       // enough blocks for 1 row/warp
    if (grid > MAXBLK) grid = MAXBLK;     // else grid-stride (4 rows/warp at B=65536)

    ghm_rows<<<grid, 256>>>(pred, target, B, C);
    ghm_reduce<<<1, 2 * BINS * 32>>>(out, grid);
}